// round 12
// baseline (speedup 1.0000x reference)
#include <cuda_runtime.h>
#include <cuda_bf16.h>
#include <cstdint>
#include <math.h>

// Problem constants
#define BB 16
#define SS 2048
#define DD 512
#define MTOT (BB*SS)          // 32768
#define KEXT 1536             // 3 * 512 (split-bf16 extended K)

// ---------------- device scratch (no allocations allowed) ----------------
// x buffers: 0 = conv-out fwd, 1 = conv-out bwd, 2 = hw1-out fwd, 3 = hw1-out bwd
__device__ __align__(128) float          g_xf[4][(size_t)MTOT * DD];
__device__ __align__(128) __nv_bfloat16  g_xh[4][(size_t)MTOT * DD];
__device__ __align__(128) __nv_bfloat16  g_xl[4][(size_t)MTOT * DD];
// packed transposed split weights: [8][N=1024][K'=1536] bf16
// index = layer*4 + dir*2 + hw ; rows n, cols k' : [0,512)=hi, [512,1024)=lo, [1024,1536)=hi
__device__ __align__(128) __nv_bfloat16  g_wt[8][(size_t)1024 * KEXT];

// ---------------- small helpers ----------------
__device__ __forceinline__ uint32_t smem_u32(const void* p) {
    return (uint32_t)__cvta_generic_to_shared(p);
}
__device__ __forceinline__ void cp16s(uint32_t s, const void* g) {
    asm volatile("cp.async.cg.shared.global [%0], [%1], 16;\n" :: "r"(s), "l"(g) : "memory");
}
__device__ __forceinline__ void cp_commit() {
    asm volatile("cp.async.commit_group;\n" ::: "memory");
}
__device__ __forceinline__ void cp_wait1() {
    asm volatile("cp.async.wait_group 1;\n" ::: "memory");
}
__device__ __forceinline__ void cp_wait0() {
    asm volatile("cp.async.wait_group 0;\n" ::: "memory");
}
__device__ __forceinline__ void ldsm4(uint32_t& r0, uint32_t& r1, uint32_t& r2, uint32_t& r3,
                                      uint32_t addr) {
    asm volatile("ldmatrix.sync.aligned.m8n8.x4.shared.b16 {%0,%1,%2,%3}, [%4];\n"
                 : "=r"(r0), "=r"(r1), "=r"(r2), "=r"(r3) : "r"(addr));
}
__device__ __forceinline__ void mma16816(float* c, const uint32_t* a, uint32_t b0, uint32_t b1) {
    asm volatile(
        "mma.sync.aligned.m16n8k16.row.col.f32.bf16.bf16.f32 "
        "{%0,%1,%2,%3},{%4,%5,%6,%7},{%8,%9},{%0,%1,%2,%3};\n"
        : "+f"(c[0]), "+f"(c[1]), "+f"(c[2]), "+f"(c[3])
        : "r"(a[0]), "r"(a[1]), "r"(a[2]), "r"(a[3]), "r"(b0), "r"(b1));
}
__device__ __forceinline__ void split_bf16(float v, __nv_bfloat16& h, __nv_bfloat16& l) {
    h = __float2bfloat16(v);
    l = __float2bfloat16(v - __bfloat162float(h));
}

// ---------------- weight prep: transpose + hi/lo split + K-extension ----------------
// grid (16, 32, 8), block (32, 8)
__global__ void prep_w_kernel(const float* __restrict__ fw_W, const float* __restrict__ bw_W) {
    __shared__ float tile[32][33];
    int wI = blockIdx.z;
    int l  = wI >> 2, dir = (wI >> 1) & 1, hw = wI & 1;
    const float* src = (dir ? bw_W : fw_W) + ((size_t)(l * 2 + hw)) * DD * 1024;
    int kb = blockIdx.x * 32, nb = blockIdx.y * 32;
    int tx = threadIdx.x, ty = threadIdx.y;
#pragma unroll
    for (int i = 0; i < 4; i++) {
        int k = kb + ty + i * 8;
        tile[ty + i * 8][tx] = src[(size_t)k * 1024 + nb + tx];
    }
    __syncthreads();
    __nv_bfloat16* dst = g_wt[wI];
#pragma unroll
    for (int i = 0; i < 4; i++) {
        int n = nb + ty + i * 8;
        int k = kb + tx;
        float v = tile[tx][ty + i * 8];
        __nv_bfloat16 h, lo;
        split_bf16(v, h, lo);
        size_t base = (size_t)n * KEXT;
        dst[base + k]        = h;
        dst[base + 512 + k]  = lo;
        dst[base + 1024 + k] = h;
    }
}

// ---------------- band conv (17 taps, scalar weights) + hi/lo emit ----------------
__global__ void band_conv_kernel(const float4* __restrict__ x, int xRow4, int xOff4,
                                 const float* __restrict__ w, int causal, int outIdx) {
    int c4 = threadIdx.x;                                  // 0..127  (4 channels each)
    int t  = blockIdx.x * blockDim.y + threadIdx.y;        // 0..2047
    int b  = blockIdx.y;
    float wr[17];
#pragma unroll
    for (int i = 0; i < 17; i++) wr[i] = w[i];

    float4 acc = make_float4(0.f, 0.f, 0.f, 0.f);
#pragma unroll
    for (int d = 0; d <= 16; d++) {
        int ts = causal ? (t - d) : (t + d);
        float wd = causal ? wr[16 - d] : wr[d];
        if (ts >= 0 && ts < SS) {
            float4 v = x[(size_t)(b * SS + ts) * xRow4 + xOff4 + c4];
            acc.x += wd * v.x; acc.y += wd * v.y; acc.z += wd * v.z; acc.w += wd * v.w;
        }
    }
    size_t o = ((size_t)(b * SS + t)) * DD + c4 * 4;
    *reinterpret_cast<float4*>(&g_xf[outIdx][o]) = acc;

    __nv_bfloat16 h0, l0, h1, l1, h2, l2, h3, l3;
    split_bf16(acc.x, h0, l0); split_bf16(acc.y, h1, l1);
    split_bf16(acc.z, h2, l2); split_bf16(acc.w, h3, l3);
    __nv_bfloat162* ph = reinterpret_cast<__nv_bfloat162*>(&g_xh[outIdx][o]);
    __nv_bfloat162* pl = reinterpret_cast<__nv_bfloat162*>(&g_xl[outIdx][o]);
    ph[0] = __nv_bfloat162(h0, h1); ph[1] = __nv_bfloat162(h2, h3);
    pl[0] = __nv_bfloat162(l0, l1); pl[1] = __nv_bfloat162(l2, l3);
}

// ---------------- fused split-bf16 GEMM + highway epilogue ----------------
// CTA tile: 128 rows x 128 B-rows (= 64 output cols, nl+gate interleaved in
// 8-row groups).  8 warps as 4(M) x 2(N): warp tile 32x64, acc 64 regs,
// 2 CTAs/SM.
// K' = 1536 in 24 chunks of 64; 3-stage cp.async ring, wait_group 1.
// ks-ROTATION: warp w walks the 4 k16 sub-steps in order (i + rot(w)) & 3,
// rot = (warp + warp>>2) & 3, so the warps sharing an SMSP sit in different
// LDSM/MMA phases -> crossbar and tensor pipes overlap instead of ping-pong.
// smem rows: 64 data + 8 pad = 72 bf16 (144B) -> ldmatrix conflict-free.
#define TROWS 128
#define CHUNKS 24
#define STAGES 3
#define ROWB  72
#define HBUF  (TROWS*ROWB*2)            // A or B bytes per stage (18432)
#define STAGE_BYTES (2*HBUF)            // 36864
#define SMEM_DYN (STAGES*STAGE_BYTES)   // 110592

__global__ __launch_bounds__(256, 2) void gemm_hw_kernel(
    int xIdx, int wIdx, const float* __restrict__ bias,
    float* __restrict__ outF, int outStride, int outOff, int outHL) {
    extern __shared__ __align__(16) __nv_bfloat16 dsm[];
    const uint32_t tSm = smem_u32(dsm);

    const __nv_bfloat16* Xh = g_xh[xIdx];
    const __nv_bfloat16* Xl = g_xl[xIdx];
    const float*         Xf = g_xf[xIdx];
    const __nv_bfloat16* Wt = g_wt[wIdx];
    float* of = outF ? outF : g_xf[outHL];

    int tid  = threadIdx.x;
    int warp = tid >> 5, lane = tid & 31;
    int mw = warp >> 1, nw = warp & 1;             // 4(M) x 2(N) warp grid
    const int rot = (warp + (warp >> 2)) & 3;      // per-warp ks phase offset
    int m0 = blockIdx.y * 128;
    int n0 = blockIdx.x * 64;

    float acc[2][8][4];
#pragma unroll
    for (int mt = 0; mt < 2; mt++)
#pragma unroll
        for (int nt = 0; nt < 8; nt++)
#pragma unroll
            for (int j = 0; j < 4; j++) acc[mt][nt][j] = 0.f;

    // ---- per-thread load slots: 4 A rows + 4 B rows, 16B each ----
    const int lrow  = tid >> 3;        // 0..31
    const int lcol8 = (tid & 7) * 8;   // 0..56 (bf16 elems)
    uint32_t aDst[4], bDst[4];
    size_t   aOff[4], bOff[4];
#pragma unroll
    for (int i = 0; i < 4; i++) {
        int row = lrow + 32 * i;       // 0..127
        aDst[i] = tSm + (uint32_t)(row * ROWB + lcol8) * 2;
        aOff[i] = (size_t)(m0 + row) * DD + lcol8;
        int nsrc = (((row >> 3) & 1) ? 512 : 0) + n0 + (row >> 4) * 8 + (row & 7);
        bDst[i] = tSm + HBUF + (uint32_t)(row * ROWB + lcol8) * 2;
        bOff[i] = (size_t)nsrc * KEXT + lcol8;
    }

    // chunk c (k64): A from Xh (c<16) else Xl, kA=(c&7)*64; B kB=c*64
    auto load_chunk = [&](int c, uint32_t so) {
        const __nv_bfloat16* Xs = (c < 16) ? Xh : Xl;
        int kA = (c & 7) * 64;
        int kB = c * 64;
#pragma unroll
        for (int i = 0; i < 4; i++) {
            cp16s(aDst[i] + so, Xs + aOff[i] + kA);
            cp16s(bDst[i] + so, Wt + bOff[i] + kB);
        }
        cp_commit();
    };

    // ---- precomputed ldsm lane addressing (stage 0) ----
    uint32_t aLd[2], bLd[4];
#pragma unroll
    for (int mt = 0; mt < 2; mt++) {
        int r   = mw * 32 + mt * 16 + (lane & 15);
        int col = (lane >> 4) * 8;
        aLd[mt] = tSm + (uint32_t)(r * ROWB + col) * 2;
    }
#pragma unroll
    for (int tp = 0; tp < 4; tp++) {
        int r   = nw * 64 + tp * 16 + ((lane >> 4) << 3) + (lane & 7);
        int col = ((lane >> 3) & 1) << 3;
        bLd[tp] = tSm + HBUF + (uint32_t)(r * ROWB + col) * 2;
    }

    load_chunk(0, 0);
    load_chunk(1, STAGE_BYTES);

    uint32_t so  = 0;                        // stage of chunk c
    uint32_t soL = 2 * STAGE_BYTES;          // stage of chunk c+2
    for (int c = 0; c < CHUNKS; c++) {
        if (c == CHUNKS - 1) cp_wait0(); else cp_wait1();
        __syncthreads();
        if (c + 2 < CHUNKS) load_chunk(c + 2, soL);

#pragma unroll
        for (int i = 0; i < 4; i++) {
            const int ks = (i + rot) & 3;                   // rotated sub-step
            const uint32_t kb = so + (uint32_t)(ks * 32);   // 16 bf16 = 32B
            uint32_t a[2][4];
#pragma unroll
            for (int mt = 0; mt < 2; mt++)
                ldsm4(a[mt][0], a[mt][1], a[mt][2], a[mt][3], aLd[mt] + kb);
#pragma unroll
            for (int tp = 0; tp < 4; tp++) {
                uint32_t b0, b1, b2, b3;
                ldsm4(b0, b1, b2, b3, bLd[tp] + kb);
#pragma unroll
                for (int mt = 0; mt < 2; mt++) {
                    mma16816(acc[mt][2 * tp],     a[mt], b0, b1);
                    mma16816(acc[mt][2 * tp + 1], a[mt], b2, b3);
                }
            }
        }
        so  = (so  == (STAGES - 1) * STAGE_BYTES) ? 0 : so  + STAGE_BYTES;
        soL = (soL == (STAGES - 1) * STAGE_BYTES) ? 0 : soL + STAGE_BYTES;
    }

    // ---- highway epilogue (in-register: n-tile 2t = nl, 2t+1 = gate) ----
    const int rbase = m0 + mw * 32 + (lane >> 2);
    const int cbase = (lane & 3) * 2;
#pragma unroll
    for (int tp = 0; tp < 4; tp++) {
#pragma unroll
        for (int j = 0; j < 2; j++) {
            int d = n0 + (4 * nw + tp) * 8 + cbase + j;
            float b_nl = __ldg(&bias[d]);
            float b_g  = __ldg(&bias[512 + d]);
#pragma unroll
            for (int mt = 0; mt < 2; mt++) {
#pragma unroll
                for (int rh = 0; rh < 2; rh++) {
                    int row = rbase + mt * 16 + rh * 8;
                    float nl = acc[mt][2 * tp][rh * 2 + j] + b_nl;
                    float gt = acc[mt][2 * tp + 1][rh * 2 + j] + b_g;
                    float g  = 1.f / (1.f + __expf(-gt));
                    float xv = Xf[(size_t)row * DD + d];
                    float y  = g * xv + (1.f - g) * fmaxf(nl, 0.f);
                    of[(size_t)row * outStride + outOff + d] = y;
                    if (outHL >= 0) {
                        __nv_bfloat16 h, lo;
                        split_bf16(y, h, lo);
                        g_xh[outHL][(size_t)row * DD + d] = h;
                        g_xl[outHL][(size_t)row * DD + d] = lo;
                    }
                }
            }
        }
    }
}

// ---------------- launch ----------------
extern "C" void kernel_launch(void* const* d_in, const int* in_sizes, int n_in,
                              void* d_out, int out_size) {
    const float* inputs  = (const float*)d_in[0];
    // d_in[1] = masks (all ones; unused by reference)
    const float* fw_band = (const float*)d_in[2];
    const float* bw_band = (const float*)d_in[3];
    const float* fw_W    = (const float*)d_in[4];
    const float* fw_b    = (const float*)d_in[5];
    const float* bw_W    = (const float*)d_in[6];
    const float* bw_b    = (const float*)d_in[7];
    float* out = (float*)d_out;

    cudaFuncSetAttribute(gemm_hw_kernel,
                         cudaFuncAttributeMaxDynamicSharedMemorySize, SMEM_DYN);

    prep_w_kernel<<<dim3(16, 32, 8), dim3(32, 8)>>>(fw_W, bw_W);

    const dim3 cg(SS / 4, BB), cb(128, 4);
    const dim3 gg(8, MTOT / 128), gb(256);
    const size_t OUT_L = (size_t)BB * SS * 1024;

    for (int l = 0; l < 2; l++) {
        const float4* xin;
        int xr4;
        if (l == 0) { xin = (const float4*)inputs; xr4 = DD / 4; }
        else        { xin = (const float4*)out;    xr4 = 1024 / 4; }  // layer-0 output
        int bwdOff4 = (l == 0) ? 0 : (512 / 4);

        band_conv_kernel<<<cg, cb>>>(xin, xr4, 0,       fw_band + l * 17, 1, 0);
        band_conv_kernel<<<cg, cb>>>(xin, xr4, bwdOff4, bw_band + l * 17, 0, 1);

        // highway 1 (writes fp32 + hi/lo into buffers 2/3)
        gemm_hw_kernel<<<gg, gb, SMEM_DYN>>>(0, l * 4 + 0, fw_b + (size_t)(l * 2) * 1024,
                                             nullptr, DD, 0, 2);
        gemm_hw_kernel<<<gg, gb, SMEM_DYN>>>(1, l * 4 + 2, bw_b + (size_t)(l * 2) * 1024,
                                             nullptr, DD, 0, 3);
        // highway 2 (writes straight into d_out slices)
        gemm_hw_kernel<<<gg, gb, SMEM_DYN>>>(2, l * 4 + 1, fw_b + (size_t)(l * 2 + 1) * 1024,
                                             out + l * OUT_L, 1024, 0, -1);
        gemm_hw_kernel<<<gg, gb, SMEM_DYN>>>(3, l * 4 + 3, bw_b + (size_t)(l * 2 + 1) * 1024,
                                             out + l * OUT_L, 1024, 512, -1);
    }
}

// round 13
// speedup vs baseline: 1.1135x; 1.1135x over previous
#include <cuda_runtime.h>
#include <cuda_bf16.h>
#include <cstdint>
#include <math.h>

// Problem constants
#define BB 16
#define SS 2048
#define DD 512
#define MTOT (BB*SS)          // 32768
#define KEXT 1536             // 3 * 512 (split-bf16 extended K)

// ---------------- device scratch (no allocations allowed) ----------------
// x buffers: 0 = conv-out fwd, 1 = conv-out bwd, 2 = hw1-out fwd, 3 = hw1-out bwd
__device__ __align__(128) float          g_xf[4][(size_t)MTOT * DD];
__device__ __align__(128) __nv_bfloat16  g_xh[4][(size_t)MTOT * DD];
__device__ __align__(128) __nv_bfloat16  g_xl[4][(size_t)MTOT * DD];
// packed transposed split weights: [8][N=1024][K'=1536] bf16
// index = layer*4 + dir*2 + hw ; rows n, cols k' : [0,512)=hi, [512,1024)=lo, [1024,1536)=hi
__device__ __align__(128) __nv_bfloat16  g_wt[8][(size_t)1024 * KEXT];

// ---------------- small helpers ----------------
__device__ __forceinline__ uint32_t smem_u32(const void* p) {
    return (uint32_t)__cvta_generic_to_shared(p);
}
__device__ __forceinline__ void cp16s(uint32_t s, const void* g) {
    asm volatile("cp.async.cg.shared.global [%0], [%1], 16;\n" :: "r"(s), "l"(g) : "memory");
}
__device__ __forceinline__ void ldsm4(uint32_t& r0, uint32_t& r1, uint32_t& r2, uint32_t& r3,
                                      uint32_t addr) {
    asm volatile("ldmatrix.sync.aligned.m8n8.x4.shared.b16 {%0,%1,%2,%3}, [%4];\n"
                 : "=r"(r0), "=r"(r1), "=r"(r2), "=r"(r3) : "r"(addr));
}
__device__ __forceinline__ void mma16816(float* c, const uint32_t* a, uint32_t b0, uint32_t b1) {
    asm volatile(
        "mma.sync.aligned.m16n8k16.row.col.f32.bf16.bf16.f32 "
        "{%0,%1,%2,%3},{%4,%5,%6,%7},{%8,%9},{%0,%1,%2,%3};\n"
        : "+f"(c[0]), "+f"(c[1]), "+f"(c[2]), "+f"(c[3])
        : "r"(a[0]), "r"(a[1]), "r"(a[2]), "r"(a[3]), "r"(b0), "r"(b1));
}
__device__ __forceinline__ void split_bf16(float v, __nv_bfloat16& h, __nv_bfloat16& l) {
    h = __float2bfloat16(v);
    l = __float2bfloat16(v - __bfloat162float(h));
}
// ---- mbarrier primitives (sm_80-class; no tcgen05) ----
__device__ __forceinline__ void mbar_init(uint32_t mbar, uint32_t cnt) {
    asm volatile("mbarrier.init.shared.b64 [%0], %1;" :: "r"(mbar), "r"(cnt) : "memory");
}
__device__ __forceinline__ void mbar_arrive(uint32_t mbar) {
    asm volatile("mbarrier.arrive.shared.b64 _, [%0];" :: "r"(mbar) : "memory");
}
// deferred arrive when this thread's prior cp.asyncs complete (.noinc: counts
// against the barrier's preset expected count)
__device__ __forceinline__ void cp_mbar_arrive(uint32_t mbar) {
    asm volatile("cp.async.mbarrier.arrive.noinc.shared::cta.b64 [%0];"
                 :: "r"(mbar) : "memory");
}
__device__ __forceinline__ void mbar_wait(uint32_t mbar, uint32_t parity) {
    asm volatile(
        "{\n\t.reg .pred P;\n\t"
        "WL%=:\n\t"
        "mbarrier.try_wait.parity.acquire.cta.shared::cta.b64 P, [%0], %1, 0x989680;\n\t"
        "@P bra.uni WD%=;\n\t"
        "bra.uni WL%=;\n\t"
        "WD%=:\n\t}"
        :: "r"(mbar), "r"(parity) : "memory");
}

// ---------------- weight prep: transpose + hi/lo split + K-extension ----------------
// grid (16, 32, 8), block (32, 8)
__global__ void prep_w_kernel(const float* __restrict__ fw_W, const float* __restrict__ bw_W) {
    __shared__ float tile[32][33];
    int wI = blockIdx.z;
    int l  = wI >> 2, dir = (wI >> 1) & 1, hw = wI & 1;
    const float* src = (dir ? bw_W : fw_W) + ((size_t)(l * 2 + hw)) * DD * 1024;
    int kb = blockIdx.x * 32, nb = blockIdx.y * 32;
    int tx = threadIdx.x, ty = threadIdx.y;
#pragma unroll
    for (int i = 0; i < 4; i++) {
        int k = kb + ty + i * 8;
        tile[ty + i * 8][tx] = src[(size_t)k * 1024 + nb + tx];
    }
    __syncthreads();
    __nv_bfloat16* dst = g_wt[wI];
#pragma unroll
    for (int i = 0; i < 4; i++) {
        int n = nb + ty + i * 8;
        int k = kb + tx;
        float v = tile[tx][ty + i * 8];
        __nv_bfloat16 h, lo;
        split_bf16(v, h, lo);
        size_t base = (size_t)n * KEXT;
        dst[base + k]        = h;
        dst[base + 512 + k]  = lo;
        dst[base + 1024 + k] = h;
    }
}

// ---------------- band conv (17 taps, scalar weights) + hi/lo emit ----------------
__global__ void band_conv_kernel(const float4* __restrict__ x, int xRow4, int xOff4,
                                 const float* __restrict__ w, int causal, int outIdx) {
    int c4 = threadIdx.x;                                  // 0..127  (4 channels each)
    int t  = blockIdx.x * blockDim.y + threadIdx.y;        // 0..2047
    int b  = blockIdx.y;
    float wr[17];
#pragma unroll
    for (int i = 0; i < 17; i++) wr[i] = w[i];

    float4 acc = make_float4(0.f, 0.f, 0.f, 0.f);
#pragma unroll
    for (int d = 0; d <= 16; d++) {
        int ts = causal ? (t - d) : (t + d);
        float wd = causal ? wr[16 - d] : wr[d];
        if (ts >= 0 && ts < SS) {
            float4 v = x[(size_t)(b * SS + ts) * xRow4 + xOff4 + c4];
            acc.x += wd * v.x; acc.y += wd * v.y; acc.z += wd * v.z; acc.w += wd * v.w;
        }
    }
    size_t o = ((size_t)(b * SS + t)) * DD + c4 * 4;
    *reinterpret_cast<float4*>(&g_xf[outIdx][o]) = acc;

    __nv_bfloat16 h0, l0, h1, l1, h2, l2, h3, l3;
    split_bf16(acc.x, h0, l0); split_bf16(acc.y, h1, l1);
    split_bf16(acc.z, h2, l2); split_bf16(acc.w, h3, l3);
    __nv_bfloat162* ph = reinterpret_cast<__nv_bfloat162*>(&g_xh[outIdx][o]);
    __nv_bfloat162* pl = reinterpret_cast<__nv_bfloat162*>(&g_xl[outIdx][o]);
    ph[0] = __nv_bfloat162(h0, h1); ph[1] = __nv_bfloat162(h2, h3);
    pl[0] = __nv_bfloat162(l0, l1); pl[1] = __nv_bfloat162(l2, l3);
}

// ---------------- fused split-bf16 GEMM + highway epilogue ----------------
// CTA tile: 128 rows x 128 B-rows (= 64 output cols, nl+gate interleaved in
// 8-row groups).  8 warps as 4(M) x 2(N): warp tile 32x64, acc 64 regs,
// 2 CTAs/SM.
// K' = 1536 in 24 chunks of 64; 3-stage ring with MBARRIER pipeline:
//   full[s]  (count 256): per-thread cp.async.mbarrier.arrive.noinc after the
//            chunk's cp.async slice -> flips when the chunk has fully landed.
//   empty[s] (count 8): one elected arrive per warp after its MMAs for the
//            chunk issued -> stage reusable.
// NO __syncthreads in the mainloop: warps free-run with up to ~2 chunks of
// skew, so LDSM phases of some warps overlap MMA phases of others.
// smem rows: 64 data + 8 pad = 72 bf16 (144B) -> ldmatrix conflict-free.
#define TROWS 128
#define CHUNKS 24
#define STAGES 3
#define ROWB  72
#define HBUF  (TROWS*ROWB*2)            // A or B bytes per stage (18432)
#define STAGE_BYTES (2*HBUF)            // 36864
#define SMEM_DYN (STAGES*STAGE_BYTES + 64)   // + mbarrier block

__global__ __launch_bounds__(256, 2) void gemm_hw_kernel(
    int xIdx, int wIdx, const float* __restrict__ bias,
    float* __restrict__ outF, int outStride, int outOff, int outHL) {
    extern __shared__ __align__(16) __nv_bfloat16 dsm[];
    const uint32_t tSm = smem_u32(dsm);
    const uint32_t mbF = tSm + STAGES * STAGE_BYTES;   // full[3]  @ +0,8,16
    const uint32_t mbE = mbF + 24;                     // empty[3] @ +24,32,40

    const __nv_bfloat16* Xh = g_xh[xIdx];
    const __nv_bfloat16* Xl = g_xl[xIdx];
    const float*         Xf = g_xf[xIdx];
    const __nv_bfloat16* Wt = g_wt[wIdx];
    float* of = outF ? outF : g_xf[outHL];

    int tid  = threadIdx.x;
    int warp = tid >> 5, lane = tid & 31;
    int mw = warp >> 1, nw = warp & 1;             // 4(M) x 2(N) warp grid
    int m0 = blockIdx.y * 128;
    int n0 = blockIdx.x * 64;

    float acc[2][8][4];
#pragma unroll
    for (int mt = 0; mt < 2; mt++)
#pragma unroll
        for (int nt = 0; nt < 8; nt++)
#pragma unroll
            for (int j = 0; j < 4; j++) acc[mt][nt][j] = 0.f;

    // ---- per-thread load slots: 4 A rows + 4 B rows, 16B each ----
    const int lrow  = tid >> 3;        // 0..31
    const int lcol8 = (tid & 7) * 8;   // 0..56 (bf16 elems)
    uint32_t aDst[4], bDst[4];
    size_t   aOff[4], bOff[4];
#pragma unroll
    for (int i = 0; i < 4; i++) {
        int row = lrow + 32 * i;       // 0..127
        aDst[i] = tSm + (uint32_t)(row * ROWB + lcol8) * 2;
        aOff[i] = (size_t)(m0 + row) * DD + lcol8;
        int nsrc = (((row >> 3) & 1) ? 512 : 0) + n0 + (row >> 4) * 8 + (row & 7);
        bDst[i] = tSm + HBUF + (uint32_t)(row * ROWB + lcol8) * 2;
        bOff[i] = (size_t)nsrc * KEXT + lcol8;
    }

    // chunk c (k64): A from Xh (c<16) else Xl, kA=(c&7)*64; B kB=c*64
    auto load_chunk = [&](int c, uint32_t so) {
        const __nv_bfloat16* Xs = (c < 16) ? Xh : Xl;
        int kA = (c & 7) * 64;
        int kB = c * 64;
#pragma unroll
        for (int i = 0; i < 4; i++) {
            cp16s(aDst[i] + so, Xs + aOff[i] + kA);
            cp16s(bDst[i] + so, Wt + bOff[i] + kB);
        }
    };

    // ---- precomputed ldsm lane addressing (stage 0) ----
    uint32_t aLd[2], bLd[4];
#pragma unroll
    for (int mt = 0; mt < 2; mt++) {
        int r   = mw * 32 + mt * 16 + (lane & 15);
        int col = (lane >> 4) * 8;
        aLd[mt] = tSm + (uint32_t)(r * ROWB + col) * 2;
    }
#pragma unroll
    for (int tp = 0; tp < 4; tp++) {
        int r   = nw * 64 + tp * 16 + ((lane >> 4) << 3) + (lane & 7);
        int col = ((lane >> 3) & 1) << 3;
        bLd[tp] = tSm + HBUF + (uint32_t)(r * ROWB + col) * 2;
    }

    // ---- barrier init ----
    if (tid == 0) {
#pragma unroll
        for (int s = 0; s < STAGES; s++) {
            mbar_init(mbF + 8u * s, 256u);   // full: all threads' cp-arrives
            mbar_init(mbE + 8u * s, 8u);     // empty: one arrive per warp
        }
    }
    __syncthreads();

    // ---- prologue: fill all 3 stages ----
#pragma unroll
    for (int s = 0; s < STAGES; s++) {
        load_chunk(s, (uint32_t)s * STAGE_BYTES);
        cp_mbar_arrive(mbF + 8u * s);
    }

    // ---- mainloop: 8 groups x 3 stages; phase parity = g & 1 ----
    for (int g = 0; g < 8; g++) {
        const uint32_t ph = (uint32_t)(g & 1);
#pragma unroll
        for (int s = 0; s < STAGES; s++) {
            const uint32_t so = (uint32_t)s * STAGE_BYTES;
            mbar_wait(mbF + 8u * s, ph);            // chunk 3g+s landed

#pragma unroll
            for (int ks = 0; ks < 4; ks++) {
                const uint32_t kb = so + (uint32_t)(ks * 32);   // 16 bf16 = 32B
                uint32_t a[2][4];
#pragma unroll
                for (int mt = 0; mt < 2; mt++)
                    ldsm4(a[mt][0], a[mt][1], a[mt][2], a[mt][3], aLd[mt] + kb);
#pragma unroll
                for (int tp = 0; tp < 4; tp++) {
                    uint32_t b0, b1, b2, b3;
                    ldsm4(b0, b1, b2, b3, bLd[tp] + kb);
#pragma unroll
                    for (int mt = 0; mt < 2; mt++) {
                        mma16816(acc[mt][2 * tp],     a[mt], b0, b1);
                        mma16816(acc[mt][2 * tp + 1], a[mt], b2, b3);
                    }
                }
            }

            if (lane == 0) mbar_arrive(mbE + 8u * s);   // this warp done with stage
            if (g < 7) {
                mbar_wait(mbE + 8u * s, ph);            // all warps done -> reusable
                load_chunk(3 * (g + 1) + s, so);
                cp_mbar_arrive(mbF + 8u * s);
            }
        }
    }

    // ---- highway epilogue (in-register: n-tile 2t = nl, 2t+1 = gate) ----
    const int rbase = m0 + mw * 32 + (lane >> 2);
    const int cbase = (lane & 3) * 2;
#pragma unroll
    for (int tp = 0; tp < 4; tp++) {
#pragma unroll
        for (int j = 0; j < 2; j++) {
            int d = n0 + (4 * nw + tp) * 8 + cbase + j;
            float b_nl = __ldg(&bias[d]);
            float b_g  = __ldg(&bias[512 + d]);
#pragma unroll
            for (int mt = 0; mt < 2; mt++) {
#pragma unroll
                for (int rh = 0; rh < 2; rh++) {
                    int row = rbase + mt * 16 + rh * 8;
                    float nl = acc[mt][2 * tp][rh * 2 + j] + b_nl;
                    float gt = acc[mt][2 * tp + 1][rh * 2 + j] + b_g;
                    float g  = 1.f / (1.f + __expf(-gt));
                    float xv = Xf[(size_t)row * DD + d];
                    float y  = g * xv + (1.f - g) * fmaxf(nl, 0.f);
                    of[(size_t)row * outStride + outOff + d] = y;
                    if (outHL >= 0) {
                        __nv_bfloat16 h, lo;
                        split_bf16(y, h, lo);
                        g_xh[outHL][(size_t)row * DD + d] = h;
                        g_xl[outHL][(size_t)row * DD + d] = lo;
                    }
                }
            }
        }
    }
}

// ---------------- launch ----------------
extern "C" void kernel_launch(void* const* d_in, const int* in_sizes, int n_in,
                              void* d_out, int out_size) {
    const float* inputs  = (const float*)d_in[0];
    // d_in[1] = masks (all ones; unused by reference)
    const float* fw_band = (const float*)d_in[2];
    const float* bw_band = (const float*)d_in[3];
    const float* fw_W    = (const float*)d_in[4];
    const float* fw_b    = (const float*)d_in[5];
    const float* bw_W    = (const float*)d_in[6];
    const float* bw_b    = (const float*)d_in[7];
    float* out = (float*)d_out;

    cudaFuncSetAttribute(gemm_hw_kernel,
                         cudaFuncAttributeMaxDynamicSharedMemorySize, SMEM_DYN);

    prep_w_kernel<<<dim3(16, 32, 8), dim3(32, 8)>>>(fw_W, bw_W);

    const dim3 cg(SS / 4, BB), cb(128, 4);
    const dim3 gg(8, MTOT / 128), gb(256);
    const size_t OUT_L = (size_t)BB * SS * 1024;

    for (int l = 0; l < 2; l++) {
        const float4* xin;
        int xr4;
        if (l == 0) { xin = (const float4*)inputs; xr4 = DD / 4; }
        else        { xin = (const float4*)out;    xr4 = 1024 / 4; }  // layer-0 output
        int bwdOff4 = (l == 0) ? 0 : (512 / 4);

        band_conv_kernel<<<cg, cb>>>(xin, xr4, 0,       fw_band + l * 17, 1, 0);
        band_conv_kernel<<<cg, cb>>>(xin, xr4, bwdOff4, bw_band + l * 17, 0, 1);

        // highway 1 (writes fp32 + hi/lo into buffers 2/3)
        gemm_hw_kernel<<<gg, gb, SMEM_DYN>>>(0, l * 4 + 0, fw_b + (size_t)(l * 2) * 1024,
                                             nullptr, DD, 0, 2);
        gemm_hw_kernel<<<gg, gb, SMEM_DYN>>>(1, l * 4 + 2, bw_b + (size_t)(l * 2) * 1024,
                                             nullptr, DD, 0, 3);
        // highway 2 (writes straight into d_out slices)
        gemm_hw_kernel<<<gg, gb, SMEM_DYN>>>(2, l * 4 + 1, fw_b + (size_t)(l * 2 + 1) * 1024,
                                             out + l * OUT_L, 1024, 0, -1);
        gemm_hw_kernel<<<gg, gb, SMEM_DYN>>>(3, l * 4 + 3, bw_b + (size_t)(l * 2 + 1) * 1024,
                                             out + l * OUT_L, 1024, 512, -1);
    }
}